// round 2
// baseline (speedup 1.0000x reference)
#include <cuda_runtime.h>

#define N_NODES 50000
#define N_EDGES 200000
#define HDIM 32
#define T_ITERS 8

// ---------------- scratch (device globals: no allocation allowed) ----------
__device__ float g_A[(size_t)N_EDGES * 1024];   // A transposed per edge: [e][j][i]
__device__ float g_m[N_NODES * HDIM];           // aggregated messages
__device__ float g_x0[N_NODES * HDIM];          // ping
__device__ float g_x1[N_NODES * HDIM];          // pong

// ---------------- packed f32x2 helpers (sm_100+) ----------------
__device__ __forceinline__ unsigned long long fma2(unsigned long long a,
                                                   unsigned long long b,
                                                   unsigned long long c) {
    unsigned long long d;
    asm("fma.rn.f32x2 %0, %1, %2, %3;" : "=l"(d) : "l"(a), "l"(b), "l"(c));
    return d;
}
__device__ __forceinline__ unsigned long long pack2(float x, float y) {
    unsigned long long d;
    asm("mov.b64 %0, {%1, %2};" : "=l"(d) : "f"(x), "f"(y));
    return d;
}
__device__ __forceinline__ float2 unpack2(unsigned long long v) {
    float2 r;
    asm("mov.b64 {%0, %1}, %2;" : "=f"(r.x), "=f"(r.y) : "l"(v));
    return r;
}

__device__ __forceinline__ float sigmoidf_(float v) {
    return 1.0f / (1.0f + __expf(-v));
}

// ============================================================
// copy input x -> g_x0
// ============================================================
__global__ void copy_x_kernel(const float* __restrict__ x) {
    int i = blockIdx.x * blockDim.x + threadIdx.x;
    if (i < N_NODES * HDIM / 4) {
        ((float4*)g_x0)[i] = ((const float4*)x)[i];
    }
}

// ============================================================
// zero g_m
// ============================================================
__global__ void zero_m_kernel() {
    int i = blockIdx.x * blockDim.x + threadIdx.x;
    if (i < N_NODES * HDIM / 4) {
        ((float4*)g_m)[i] = make_float4(0.f, 0.f, 0.f, 0.f);
    }
}

// ============================================================
// Edge MLP:
//   hid = relu(edge_data @ W1^T + b1)            [E,64]
//   A   = relu(hid @ W2^T + b2)                  [E,1024], stored [e][j][i]
// One block = 64 edges, 256 threads.
// Phase 2 uses f32x2 FMA with 4-edge x 4-output register tiles.
// Output index q = j*32 + i  (store-layout order -> coalesced float4 stores);
// the W2 row needed for q is o = i*32 + j = ((q&31)<<5) | (q>>5), applied as a
// permutation during the W2 smem staging.
// ============================================================
__global__ __launch_bounds__(256) void edge_mlp_kernel(
    const float* __restrict__ ed, const float* __restrict__ W1,
    const float* __restrict__ b1, const float* __restrict__ W2,
    const float* __restrict__ b2)
{
    __shared__ float s_hid[64][65];   // [edge][k], pad 65 -> conflict-free
    __shared__ float s_w[64][68];     // [k][q] for current 64-q tile, pad 68 (16B-aligned rows)

    const int tid = threadIdx.x;
    const size_t e0 = (size_t)blockIdx.x * 64;

    // ---------- phase 1: hid ----------
    {
        const int o  = tid & 63;         // hidden unit
        const int eg = (tid >> 6) * 16;  // 4 groups x 16 edges
        float w[16];
        #pragma unroll
        for (int q = 0; q < 4; q++) {
            float4 v = __ldg((const float4*)(W1 + o * 16) + q);
            w[4*q+0] = v.x; w[4*q+1] = v.y; w[4*q+2] = v.z; w[4*q+3] = v.w;
        }
        const float bb = __ldg(b1 + o);
        #pragma unroll 4
        for (int ii = 0; ii < 16; ii++) {
            const size_t e = e0 + (size_t)(eg + ii);
            const float4* ep = (const float4*)(ed + e * 16);
            float acc = bb;
            #pragma unroll
            for (int q = 0; q < 4; q++) {
                float4 v = __ldg(ep + q);
                acc += v.x * w[4*q+0] + v.y * w[4*q+1]
                     + v.z * w[4*q+2] + v.w * w[4*q+3];
            }
            s_hid[eg + ii][o] = fmaxf(acc, 0.f);
        }
    }
    __syncthreads();

    const int qx = (tid & 15) * 4;   // 4 q-outputs per thread
    const int ey = (tid >> 4) * 4;   // 4 edges per thread

    for (int qt = 0; qt < 16; qt++) {
        if (qt) __syncthreads();   // protect s_w from previous tile's readers

        // ---- stage W2 tile, transposed + q->o permuted ----
        #pragma unroll
        for (int r = 0; r < 4; r++) {
            const int lin = tid + r * 256;      // 1024 float4 slots
            const int q   = lin & 63;
            const int k4  = lin >> 6;
            const int qg  = qt * 64 + q;
            const int o   = ((qg & 31) << 5) | (qg >> 5);
            float4 v = __ldg((const float4*)(W2 + (size_t)o * 64) + k4);
            s_w[4*k4+0][q] = v.x;
            s_w[4*k4+1][q] = v.y;
            s_w[4*k4+2][q] = v.z;
            s_w[4*k4+3][q] = v.w;
        }
        __syncthreads();

        // ---- bias init (pairs) ----
        float bq[4];
        #pragma unroll
        for (int c = 0; c < 4; c++) {
            const int qg = qt * 64 + qx + c;
            const int o  = ((qg & 31) << 5) | (qg >> 5);
            bq[c] = __ldg(b2 + o);
        }
        const unsigned long long bp0 = pack2(bq[0], bq[1]);
        const unsigned long long bp1 = pack2(bq[2], bq[3]);

        unsigned long long acc[4][2];
        #pragma unroll
        for (int je = 0; je < 4; je++) { acc[je][0] = bp0; acc[je][1] = bp1; }

        // ---- main FMA2 loop over k ----
        #pragma unroll 4
        for (int k = 0; k < 64; k++) {
            const ulonglong2 wv = *(const ulonglong2*)&s_w[k][qx];
            #pragma unroll
            for (int je = 0; je < 4; je++) {
                const float h = s_hid[ey + je][k];
                const unsigned long long hd = pack2(h, h);
                acc[je][0] = fma2(wv.x, hd, acc[je][0]);
                acc[je][1] = fma2(wv.y, hd, acc[je][1]);
            }
        }

        // ---- relu + coalesced float4 store into [e][j][i] layout ----
        #pragma unroll
        for (int je = 0; je < 4; je++) {
            const float2 a0 = unpack2(acc[je][0]);
            const float2 a1 = unpack2(acc[je][1]);
            float4 v = make_float4(fmaxf(a0.x, 0.f), fmaxf(a0.y, 0.f),
                                   fmaxf(a1.x, 0.f), fmaxf(a1.y, 0.f));
            *(float4*)(g_A + (e0 + (size_t)(ey + je)) * 1024 + qt * 64 + qx) = v;
        }
    }
}

// ============================================================
// Message pass: warp per edge.
//   msg_i = sum_j A[e][i][j] * x[src][j]   (A stored [e][j][i] -> coalesced)
//   atomicAdd into m[src], and m[dst] if src != dst.
// ============================================================
__global__ __launch_bounds__(256) void msg_kernel(const int* __restrict__ edges, int t) {
    const float* __restrict__ xc = (t & 1) ? g_x1 : g_x0;

    const int warp = (blockIdx.x * blockDim.x + threadIdx.x) >> 5;
    const int lane = threadIdx.x & 31;
    if (warp >= N_EDGES) return;

    const int src = __ldg(edges + 2 * warp);
    const int dst = __ldg(edges + 2 * warp + 1);

    const float xv = __ldg(xc + (size_t)src * HDIM + lane);
    const float* Ap = g_A + (size_t)warp * 1024 + lane;

    float acc = 0.f;
    #pragma unroll
    for (int j = 0; j < 32; j++) {
        const float a  = __ldg(Ap + j * 32);
        const float xj = __shfl_sync(0xffffffffu, xv, j);
        acc = fmaf(a, xj, acc);
    }

    atomicAdd(g_m + (size_t)src * HDIM + lane, acc);
    if (src != dst) atomicAdd(g_m + (size_t)dst * HDIM + lane, acc);
}

// ============================================================
// GRU cell: thread per node. W staged in smem (broadcast reads),
// x/m in registers. inp = [x, m]:
//   gi = W_ih @ inp + b_ih   (rows: r=0..31, z=32..63, n=64..95; cols 0..31=x, 32..63=m)
//   gh = W_hh @ x   + b_hh
//   r = sig(i_r+h_r); z = sig(i_z+h_z); n = tanh(i_n + r*h_n)
//   x' = (1-z)*n + z*x
// ============================================================
__global__ __launch_bounds__(256) void gru_kernel(
    const float* __restrict__ W_ih, const float* __restrict__ W_hh,
    const float* __restrict__ b_ih, const float* __restrict__ b_hh,
    float* __restrict__ dout, int t)
{
    __shared__ float s_wih[96 * 64];
    __shared__ float s_whh[96 * 32];

    const float* __restrict__ xc = (t & 1) ? g_x1 : g_x0;
    float* __restrict__ xo = (t == T_ITERS - 1) ? dout : ((t & 1) ? g_x0 : g_x1);

    for (int idx = threadIdx.x; idx < 96 * 64; idx += 256) s_wih[idx] = __ldg(W_ih + idx);
    for (int idx = threadIdx.x; idx < 96 * 32; idx += 256) s_whh[idx] = __ldg(W_hh + idx);
    __syncthreads();

    const int n = blockIdx.x * 256 + threadIdx.x;
    const bool valid = (n < N_NODES);
    const int nn_ = valid ? n : (N_NODES - 1);

    const float4* xp = (const float4*)(xc + (size_t)nn_ * HDIM);
    const float4* mp = (const float4*)(g_m + (size_t)nn_ * HDIM);
    float4 x4[8], m4[8];
    #pragma unroll
    for (int k4 = 0; k4 < 8; k4++) { x4[k4] = __ldg(xp + k4); m4[k4] = __ldg(mp + k4); }

    for (int oc = 0; oc < 8; oc++) {
        const int ob = oc * 4;
        float ir[4], iz[4], in_[4], hr[4], hz[4], hn[4];
        #pragma unroll
        for (int c = 0; c < 4; c++) {
            ir[c] = __ldg(b_ih + ob + c);
            iz[c] = __ldg(b_ih + 32 + ob + c);
            in_[c] = __ldg(b_ih + 64 + ob + c);
            hr[c] = __ldg(b_hh + ob + c);
            hz[c] = __ldg(b_hh + 32 + ob + c);
            hn[c] = __ldg(b_hh + 64 + ob + c);
        }

        #pragma unroll
        for (int k4 = 0; k4 < 8; k4++) {
            const float4 xv = x4[k4];
            const float4 mv = m4[k4];
            #pragma unroll
            for (int c = 0; c < 4; c++) {
                const float* wr = s_wih + (size_t)(ob + c) * 64;
                const float* wz = s_wih + (size_t)(32 + ob + c) * 64;
                const float* wn = s_wih + (size_t)(64 + ob + c) * 64;

                float4 a;
                a = *(const float4*)(wr + 4 * k4);
                ir[c] += a.x * xv.x + a.y * xv.y + a.z * xv.z + a.w * xv.w;
                a = *(const float4*)(wr + 32 + 4 * k4);
                ir[c] += a.x * mv.x + a.y * mv.y + a.z * mv.z + a.w * mv.w;

                a = *(const float4*)(wz + 4 * k4);
                iz[c] += a.x * xv.x + a.y * xv.y + a.z * xv.z + a.w * xv.w;
                a = *(const float4*)(wz + 32 + 4 * k4);
                iz[c] += a.x * mv.x + a.y * mv.y + a.z * mv.z + a.w * mv.w;

                a = *(const float4*)(wn + 4 * k4);
                in_[c] += a.x * xv.x + a.y * xv.y + a.z * xv.z + a.w * xv.w;
                a = *(const float4*)(wn + 32 + 4 * k4);
                in_[c] += a.x * mv.x + a.y * mv.y + a.z * mv.z + a.w * mv.w;

                a = *(const float4*)(s_whh + (size_t)(ob + c) * 32 + 4 * k4);
                hr[c] += a.x * xv.x + a.y * xv.y + a.z * xv.z + a.w * xv.w;
                a = *(const float4*)(s_whh + (size_t)(32 + ob + c) * 32 + 4 * k4);
                hz[c] += a.x * xv.x + a.y * xv.y + a.z * xv.z + a.w * xv.w;
                a = *(const float4*)(s_whh + (size_t)(64 + ob + c) * 32 + 4 * k4);
                hn[c] += a.x * xv.x + a.y * xv.y + a.z * xv.z + a.w * xv.w;
            }
        }

        float outv[4];
        #pragma unroll
        for (int c = 0; c < 4; c++) {
            const float r = sigmoidf_(ir[c] + hr[c]);
            const float z = sigmoidf_(iz[c] + hz[c]);
            const float nn2 = tanhf(in_[c] + r * hn[c]);
            const float hp = __ldg(xc + (size_t)nn_ * HDIM + ob + c);
            outv[c] = (1.f - z) * nn2 + z * hp;
        }
        if (valid) {
            *(float4*)(xo + (size_t)n * HDIM + ob) =
                make_float4(outv[0], outv[1], outv[2], outv[3]);
        }
    }
}

// ============================================================
// launch
// ============================================================
extern "C" void kernel_launch(void* const* d_in, const int* in_sizes, int n_in,
                              void* d_out, int out_size) {
    const float* x     = (const float*)d_in[0];
    const float* ed    = (const float*)d_in[1];
    const int*   edges = (const int*)d_in[2];
    // Weights are the last 8 inputs regardless of whether scalar T is materialized.
    const int wb = n_in - 8;
    const float* W1   = (const float*)d_in[wb + 0];
    const float* b1   = (const float*)d_in[wb + 1];
    const float* W2   = (const float*)d_in[wb + 2];
    const float* b2   = (const float*)d_in[wb + 3];
    const float* W_ih = (const float*)d_in[wb + 4];
    const float* W_hh = (const float*)d_in[wb + 5];
    const float* b_ih = (const float*)d_in[wb + 6];
    const float* b_hh = (const float*)d_in[wb + 7];
    float* out = (float*)d_out;

    const int n4 = N_NODES * HDIM / 4;
    const int g4 = (n4 + 255) / 256;

    copy_x_kernel<<<g4, 256>>>(x);
    edge_mlp_kernel<<<N_EDGES / 64, 256>>>(ed, W1, b1, W2, b2);

    const int msg_grid = N_EDGES / 8;              // warp per edge, 8 warps/block
    const int gru_grid = (N_NODES + 255) / 256;

    for (int t = 0; t < T_ITERS; t++) {
        zero_m_kernel<<<g4, 256>>>();
        msg_kernel<<<msg_grid, 256>>>(edges, t);
        gru_kernel<<<gru_grid, 256>>>(W_ih, W_hh, b_ih, b_hh, out, t);
    }
}

// round 4
// speedup vs baseline: 1.0815x; 1.0815x over previous
#include <cuda_runtime.h>

#define N_NODES 50000
#define N_EDGES 200000
#define HDIM 32
#define T_ITERS 8

// ---------------- scratch (device globals: no allocation allowed) ----------
__device__ float g_A[(size_t)N_EDGES * 1024];   // A per edge, fp32, layout [e][j][i]
__device__ float g_m[N_NODES * HDIM];           // aggregated messages
__device__ float g_x0[N_NODES * HDIM];          // ping
__device__ float g_x1[N_NODES * HDIM];          // pong

// ---------------- packed f32x2 helpers (sm_100+) ----------------
__device__ __forceinline__ unsigned long long fma2(unsigned long long a,
                                                   unsigned long long b,
                                                   unsigned long long c) {
    unsigned long long d;
    asm("fma.rn.f32x2 %0, %1, %2, %3;" : "=l"(d) : "l"(a), "l"(b), "l"(c));
    return d;
}
__device__ __forceinline__ unsigned long long pack2(float x, float y) {
    unsigned long long d;
    asm("mov.b64 %0, {%1, %2};" : "=l"(d) : "f"(x), "f"(y));
    return d;
}
__device__ __forceinline__ float2 unpack2(unsigned long long v) {
    float2 r;
    asm("mov.b64 {%0, %1}, %2;" : "=f"(r.x), "=f"(r.y) : "l"(v));
    return r;
}
__device__ __forceinline__ float sigmoidf_(float v) {
    return 1.0f / (1.0f + __expf(-v));
}

// ============================================================
// copy input x -> g_x0, zero g_m
// ============================================================
__global__ void copy_x_kernel(const float* __restrict__ x) {
    int i = blockIdx.x * blockDim.x + threadIdx.x;
    if (i < N_NODES * HDIM / 4) {
        ((float4*)g_x0)[i] = ((const float4*)x)[i];
        ((float4*)g_m)[i]  = make_float4(0.f, 0.f, 0.f, 0.f);
    }
}

// ============================================================
// Edge MLP:
//   hid = relu(edge_data @ W1^T + b1)            [E,64]
//   A   = relu(hid @ W2^T + b2)                  [E,1024], fp32, stored [e][j][i]
//
// Block = 64 edges, 256 threads. Phase 2: 8 q-tiles of 128 outputs.
// Stored output index q = j*32+i; W2 row needed is o = i*32+j = ((q&31)<<5)|(q>>5).
//
// smem:
//  s_h2: [k][2e] hid duplicated pairs {h,h}, row stride 132 words (16B aligned)
//  s_w : [k][q] k-major, 128 words/row, float4 chunks XOR-swizzled:
//        physical chunk p = (q>>2) ^ ((k>>2)&7)
//        -> inner LDS.128 (fixed k, m-varying lanes) conflict-free.
//
// Inner loop per k: 2 LDS.128 (w pairs) + 2 LDS.128 (h dup pair broadcast)
//   + 16 FFMA2 = 32 MACs -> FFMA2-pipe bound.
// ============================================================
__global__ __launch_bounds__(256, 2) void edge_mlp_kernel(
    const float* __restrict__ ed, const float* __restrict__ W1,
    const float* __restrict__ b1, const float* __restrict__ W2,
    const float* __restrict__ b2)
{
    __shared__ float s_h2[64 * 132];  // [k][2e]
    __shared__ float s_w[64 * 128];   // [k][swizzled q]

    const int tid = threadIdx.x;
    const size_t e0 = (size_t)blockIdx.x * 64;

    // ---------- phase 1: hid (duplicated pairs into s_h2) ----------
    {
        const int o  = tid & 63;         // hidden unit k
        const int eg = (tid >> 6) * 16;  // 4 groups x 16 edges
        float w[16];
        #pragma unroll
        for (int q = 0; q < 4; q++) {
            float4 v = __ldg((const float4*)(W1 + o * 16) + q);
            w[4*q+0] = v.x; w[4*q+1] = v.y; w[4*q+2] = v.z; w[4*q+3] = v.w;
        }
        const float bb = __ldg(b1 + o);
        #pragma unroll 4
        for (int ii = 0; ii < 16; ii++) {
            const int e = eg + ii;
            const float4* ep = (const float4*)(ed + (e0 + e) * 16);
            float acc = bb;
            #pragma unroll
            for (int q = 0; q < 4; q++) {
                float4 v = __ldg(ep + q);
                acc += v.x * w[4*q+0] + v.y * w[4*q+1]
                     + v.z * w[4*q+2] + v.w * w[4*q+3];
            }
            acc = fmaxf(acc, 0.f);
            s_h2[o * 132 + 2 * e + 0] = acc;
            s_h2[o * 132 + 2 * e + 1] = acc;
        }
    }
    __syncthreads();

    const int m  = tid & 15;         // q-chunk id (chunks m and m+16)
    const int ey = (tid >> 4) * 4;   // 4 edges per thread

    for (int qt = 0; qt < 8; qt++) {
        if (qt) __syncthreads();  // protect s_w from previous tile's readers

        // ---- stage W2 tile: transpose + permute + swizzle ----
        #pragma unroll
        for (int r = 0; r < 8; r++) {
            const int slot = tid + r * 256;   // 2048 slots
            const int q   = slot >> 4;        // 0..127
            const int k4  = slot & 15;        // 0..15
            const int qg  = qt * 128 + q;
            const int o   = ((qg & 31) << 5) | (qg >> 5);
            float4 v = __ldg((const float4*)(W2 + (size_t)o * 64) + k4);
            const int qlo = q & 3;
            const int qc  = q >> 2;
            #pragma unroll
            for (int c = 0; c < 4; c++) {
                const int k = 4 * k4 + c;
                const int p = qc ^ ((k >> 2) & 7);
                const float vv = (c == 0) ? v.x : (c == 1) ? v.y : (c == 2) ? v.z : v.w;
                s_w[k * 128 + 4 * p + qlo] = vv;
            }
        }
        __syncthreads();

        // ---- bias init ----
        float bq[8];
        #pragma unroll
        for (int c = 0; c < 8; c++) {
            const int qg = qt * 128 + ((c < 4) ? (4 * m + c) : (64 + 4 * m + (c - 4)));
            const int o  = ((qg & 31) << 5) | (qg >> 5);
            bq[c] = __ldg(b2 + o);
        }
        unsigned long long acc[4][4];
        {
            const unsigned long long p0 = pack2(bq[0], bq[1]);
            const unsigned long long p1 = pack2(bq[2], bq[3]);
            const unsigned long long p2 = pack2(bq[4], bq[5]);
            const unsigned long long p3 = pack2(bq[6], bq[7]);
            #pragma unroll
            for (int je = 0; je < 4; je++) {
                acc[je][0] = p0; acc[je][1] = p1; acc[je][2] = p2; acc[je][3] = p3;
            }
        }

        // ---- main FFMA2 loop over k ----
        #pragma unroll 8
        for (int k = 0; k < 64; k++) {
            const int s = (k >> 2) & 7;
            const float* wrow = s_w + k * 128;
            const ulonglong2 wA = *(const ulonglong2*)(wrow + 4 * (m ^ s));
            const ulonglong2 wB = *(const ulonglong2*)(wrow + 4 * ((m ^ s) + 16));
            const float* hrow = s_h2 + k * 132 + 2 * ey;
            const ulonglong2 hA = *(const ulonglong2*)(hrow);      // edges ey, ey+1
            const ulonglong2 hB = *(const ulonglong2*)(hrow + 4);  // edges ey+2, ey+3
            acc[0][0] = fma2(wA.x, hA.x, acc[0][0]);
            acc[0][1] = fma2(wA.y, hA.x, acc[0][1]);
            acc[0][2] = fma2(wB.x, hA.x, acc[0][2]);
            acc[0][3] = fma2(wB.y, hA.x, acc[0][3]);
            acc[1][0] = fma2(wA.x, hA.y, acc[1][0]);
            acc[1][1] = fma2(wA.y, hA.y, acc[1][1]);
            acc[1][2] = fma2(wB.x, hA.y, acc[1][2]);
            acc[1][3] = fma2(wB.y, hA.y, acc[1][3]);
            acc[2][0] = fma2(wA.x, hB.x, acc[2][0]);
            acc[2][1] = fma2(wA.y, hB.x, acc[2][1]);
            acc[2][2] = fma2(wB.x, hB.x, acc[2][2]);
            acc[2][3] = fma2(wB.y, hB.x, acc[2][3]);
            acc[3][0] = fma2(wA.x, hB.y, acc[3][0]);
            acc[3][1] = fma2(wA.y, hB.y, acc[3][1]);
            acc[3][2] = fma2(wB.x, hB.y, acc[3][2]);
            acc[3][3] = fma2(wB.y, hB.y, acc[3][3]);
        }

        // ---- relu + coalesced float4 stores (fp32) ----
        #pragma unroll
        for (int je = 0; je < 4; je++) {
            float* base = g_A + (e0 + ey + je) * 1024 + qt * 128;
            const float2 a0 = unpack2(acc[je][0]);
            const float2 a1 = unpack2(acc[je][1]);
            const float2 a2 = unpack2(acc[je][2]);
            const float2 a3 = unpack2(acc[je][3]);
            *(float4*)(base + 4 * m) =
                make_float4(fmaxf(a0.x, 0.f), fmaxf(a0.y, 0.f),
                            fmaxf(a1.x, 0.f), fmaxf(a1.y, 0.f));
            *(float4*)(base + 64 + 4 * m) =
                make_float4(fmaxf(a2.x, 0.f), fmaxf(a2.y, 0.f),
                            fmaxf(a3.x, 0.f), fmaxf(a3.y, 0.f));
        }
    }
}

// ============================================================
// Message pass: warp per edge.
//   msg_i = sum_j A[e][i][j] * x[src][j]   (A stored [e][j][i] -> coalesced)
//   atomicAdd into m[src], and m[dst] if src != dst.
// ============================================================
__global__ __launch_bounds__(256) void msg_kernel(const int* __restrict__ edges, int t) {
    const float* __restrict__ xc = (t & 1) ? g_x1 : g_x0;

    const int warp = (blockIdx.x * blockDim.x + threadIdx.x) >> 5;
    const int lane = threadIdx.x & 31;
    if (warp >= N_EDGES) return;

    const int src = __ldg(edges + 2 * warp);
    const int dst = __ldg(edges + 2 * warp + 1);

    const float xv = __ldg(xc + (size_t)src * HDIM + lane);
    const float* Ap = g_A + (size_t)warp * 1024 + lane;

    float acc = 0.f;
    #pragma unroll
    for (int j = 0; j < 32; j++) {
        const float a  = __ldg(Ap + j * 32);
        const float xj = __shfl_sync(0xffffffffu, xv, j);
        acc = fmaf(a, xj, acc);
    }

    atomicAdd(g_m + (size_t)src * HDIM + lane, acc);
    if (src != dst) atomicAdd(g_m + (size_t)dst * HDIM + lane, acc);
}

// ============================================================
// GRU cell: thread per node. W staged in smem (broadcast reads),
// x/m in registers. Also zeroes g_m for the next iteration.
// ============================================================
__global__ __launch_bounds__(256) void gru_kernel(
    const float* __restrict__ W_ih, const float* __restrict__ W_hh,
    const float* __restrict__ b_ih, const float* __restrict__ b_hh,
    float* __restrict__ dout, int t)
{
    __shared__ float s_wih[96 * 64];
    __shared__ float s_whh[96 * 32];

    const float* __restrict__ xc = (t & 1) ? g_x1 : g_x0;
    float* __restrict__ xo = (t == T_ITERS - 1) ? dout : ((t & 1) ? g_x0 : g_x1);

    for (int idx = threadIdx.x; idx < 96 * 64; idx += 256) s_wih[idx] = __ldg(W_ih + idx);
    for (int idx = threadIdx.x; idx < 96 * 32; idx += 256) s_whh[idx] = __ldg(W_hh + idx);
    __syncthreads();

    const int n = blockIdx.x * 256 + threadIdx.x;
    const bool valid = (n < N_NODES);
    const int nn_ = valid ? n : (N_NODES - 1);

    const float4* xp = (const float4*)(xc + (size_t)nn_ * HDIM);
    float4* mp = (float4*)(g_m + (size_t)nn_ * HDIM);
    float4 x4[8], m4[8];
    #pragma unroll
    for (int k4 = 0; k4 < 8; k4++) { x4[k4] = __ldg(xp + k4); m4[k4] = mp[k4]; }
    // zero m for the next iteration's atomics
    if (valid) {
        #pragma unroll
        for (int k4 = 0; k4 < 8; k4++) mp[k4] = make_float4(0.f, 0.f, 0.f, 0.f);
    }

    for (int oc = 0; oc < 8; oc++) {
        const int ob = oc * 4;
        float ir[4], iz[4], in_[4], hr[4], hz[4], hn[4];
        #pragma unroll
        for (int c = 0; c < 4; c++) {
            ir[c] = __ldg(b_ih + ob + c);
            iz[c] = __ldg(b_ih + 32 + ob + c);
            in_[c] = __ldg(b_ih + 64 + ob + c);
            hr[c] = __ldg(b_hh + ob + c);
            hz[c] = __ldg(b_hh + 32 + ob + c);
            hn[c] = __ldg(b_hh + 64 + ob + c);
        }

        #pragma unroll
        for (int k4 = 0; k4 < 8; k4++) {
            const float4 xv = x4[k4];
            const float4 mv = m4[k4];
            #pragma unroll
            for (int c = 0; c < 4; c++) {
                const float* wr = s_wih + (size_t)(ob + c) * 64;
                const float* wz = s_wih + (size_t)(32 + ob + c) * 64;
                const float* wn = s_wih + (size_t)(64 + ob + c) * 64;

                float4 a;
                a = *(const float4*)(wr + 4 * k4);
                ir[c] += a.x * xv.x + a.y * xv.y + a.z * xv.z + a.w * xv.w;
                a = *(const float4*)(wr + 32 + 4 * k4);
                ir[c] += a.x * mv.x + a.y * mv.y + a.z * mv.z + a.w * mv.w;

                a = *(const float4*)(wz + 4 * k4);
                iz[c] += a.x * xv.x + a.y * xv.y + a.z * xv.z + a.w * xv.w;
                a = *(const float4*)(wz + 32 + 4 * k4);
                iz[c] += a.x * mv.x + a.y * mv.y + a.z * mv.z + a.w * mv.w;

                a = *(const float4*)(wn + 4 * k4);
                in_[c] += a.x * xv.x + a.y * xv.y + a.z * xv.z + a.w * xv.w;
                a = *(const float4*)(wn + 32 + 4 * k4);
                in_[c] += a.x * mv.x + a.y * mv.y + a.z * mv.z + a.w * mv.w;

                a = *(const float4*)(s_whh + (size_t)(ob + c) * 32 + 4 * k4);
                hr[c] += a.x * xv.x + a.y * xv.y + a.z * xv.z + a.w * xv.w;
                a = *(const float4*)(s_whh + (size_t)(32 + ob + c) * 32 + 4 * k4);
                hz[c] += a.x * xv.x + a.y * xv.y + a.z * xv.z + a.w * xv.w;
                a = *(const float4*)(s_whh + (size_t)(64 + ob + c) * 32 + 4 * k4);
                hn[c] += a.x * xv.x + a.y * xv.y + a.z * xv.z + a.w * xv.w;
            }
        }

        float outv[4];
        const float* xchunk = (const float*)&x4[oc];
        #pragma unroll
        for (int c = 0; c < 4; c++) {
            const float r = sigmoidf_(ir[c] + hr[c]);
            const float z = sigmoidf_(iz[c] + hz[c]);
            const float nn2 = tanhf(in_[c] + r * hn[c]);
            outv[c] = (1.f - z) * nn2 + z * xchunk[c];
        }
        if (valid) {
            *(float4*)(xo + (size_t)n * HDIM + ob) =
                make_float4(outv[0], outv[1], outv[2], outv[3]);
        }
    }
}

// ============================================================
// launch
// ============================================================
extern "C" void kernel_launch(void* const* d_in, const int* in_sizes, int n_in,
                              void* d_out, int out_size) {
    const float* x     = (const float*)d_in[0];
    const float* ed    = (const float*)d_in[1];
    const int*   edges = (const int*)d_in[2];
    const int wb = n_in - 8;   // weights are the last 8 inputs
    const float* W1   = (const float*)d_in[wb + 0];
    const float* b1   = (const float*)d_in[wb + 1];
    const float* W2   = (const float*)d_in[wb + 2];
    const float* b2   = (const float*)d_in[wb + 3];
    const float* W_ih = (const float*)d_in[wb + 4];
    const float* W_hh = (const float*)d_in[wb + 5];
    const float* b_ih = (const float*)d_in[wb + 6];
    const float* b_hh = (const float*)d_in[wb + 7];
    float* out = (float*)d_out;

    const int n4 = N_NODES * HDIM / 4;
    const int g4 = (n4 + 255) / 256;

    copy_x_kernel<<<g4, 256>>>(x);
    edge_mlp_kernel<<<N_EDGES / 64, 256>>>(ed, W1, b1, W2, b2);

    const int msg_grid = N_EDGES / 8;              // warp per edge, 8 warps/block
    const int gru_grid = (N_NODES + 255) / 256;

    for (int t = 0; t < T_ITERS; t++) {
        msg_kernel<<<msg_grid, 256>>>(edges, t);
        gru_kernel<<<gru_grid, 256>>>(W_ih, W_hh, b_ih, b_hh, out, t);
    }
}

// round 5
// speedup vs baseline: 1.2556x; 1.1610x over previous
#include <cuda_runtime.h>

#define N_NODES 50000
#define N_EDGES 200000
#define HDIM 32
#define T_ITERS 8

// ---------------- scratch (device globals: no allocation allowed) ----------
__device__ float g_A[(size_t)N_EDGES * 1024];   // A per edge, fp32, layout [e][j][i]
__device__ float g_m[N_NODES * HDIM];           // aggregated messages
__device__ float g_x0[N_NODES * HDIM];          // ping
__device__ float g_x1[N_NODES * HDIM];          // pong

// ---------------- packed f32x2 helpers (sm_100+) ----------------
__device__ __forceinline__ unsigned long long fma2(unsigned long long a,
                                                   unsigned long long b,
                                                   unsigned long long c) {
    unsigned long long d;
    asm("fma.rn.f32x2 %0, %1, %2, %3;" : "=l"(d) : "l"(a), "l"(b), "l"(c));
    return d;
}
__device__ __forceinline__ unsigned long long pack2(float x, float y) {
    unsigned long long d;
    asm("mov.b64 %0, {%1, %2};" : "=l"(d) : "f"(x), "f"(y));
    return d;
}
__device__ __forceinline__ float2 unpack2(unsigned long long v) {
    float2 r;
    asm("mov.b64 {%0, %1}, %2;" : "=f"(r.x), "=f"(r.y) : "l"(v));
    return r;
}
__device__ __forceinline__ float sigmoidf_(float v) {
    return 1.0f / (1.0f + __expf(-v));
}

// ============================================================
// copy input x -> g_x0, zero g_m
// ============================================================
__global__ void copy_x_kernel(const float* __restrict__ x) {
    int i = blockIdx.x * blockDim.x + threadIdx.x;
    if (i < N_NODES * HDIM / 4) {
        ((float4*)g_x0)[i] = ((const float4*)x)[i];
        ((float4*)g_m)[i]  = make_float4(0.f, 0.f, 0.f, 0.f);
    }
}

// ============================================================
// Edge MLP (unchanged from R4 — proven):
//   hid = relu(edge_data @ W1^T + b1)            [E,64]
//   A   = relu(hid @ W2^T + b2)                  [E,1024], fp32, stored [e][j][i]
// ============================================================
__global__ __launch_bounds__(256, 2) void edge_mlp_kernel(
    const float* __restrict__ ed, const float* __restrict__ W1,
    const float* __restrict__ b1, const float* __restrict__ W2,
    const float* __restrict__ b2)
{
    __shared__ float s_h2[64 * 132];  // [k][2e]
    __shared__ float s_w[64 * 128];   // [k][swizzled q]

    const int tid = threadIdx.x;
    const size_t e0 = (size_t)blockIdx.x * 64;

    // ---------- phase 1: hid (duplicated pairs into s_h2) ----------
    {
        const int o  = tid & 63;
        const int eg = (tid >> 6) * 16;
        float w[16];
        #pragma unroll
        for (int q = 0; q < 4; q++) {
            float4 v = __ldg((const float4*)(W1 + o * 16) + q);
            w[4*q+0] = v.x; w[4*q+1] = v.y; w[4*q+2] = v.z; w[4*q+3] = v.w;
        }
        const float bb = __ldg(b1 + o);
        #pragma unroll 4
        for (int ii = 0; ii < 16; ii++) {
            const int e = eg + ii;
            const float4* ep = (const float4*)(ed + (e0 + e) * 16);
            float acc = bb;
            #pragma unroll
            for (int q = 0; q < 4; q++) {
                float4 v = __ldg(ep + q);
                acc += v.x * w[4*q+0] + v.y * w[4*q+1]
                     + v.z * w[4*q+2] + v.w * w[4*q+3];
            }
            acc = fmaxf(acc, 0.f);
            s_h2[o * 132 + 2 * e + 0] = acc;
            s_h2[o * 132 + 2 * e + 1] = acc;
        }
    }
    __syncthreads();

    const int m  = tid & 15;
    const int ey = (tid >> 4) * 4;

    for (int qt = 0; qt < 8; qt++) {
        if (qt) __syncthreads();

        #pragma unroll
        for (int r = 0; r < 8; r++) {
            const int slot = tid + r * 256;
            const int q   = slot >> 4;
            const int k4  = slot & 15;
            const int qg  = qt * 128 + q;
            const int o   = ((qg & 31) << 5) | (qg >> 5);
            float4 v = __ldg((const float4*)(W2 + (size_t)o * 64) + k4);
            const int qlo = q & 3;
            const int qc  = q >> 2;
            #pragma unroll
            for (int c = 0; c < 4; c++) {
                const int k = 4 * k4 + c;
                const int p = qc ^ ((k >> 2) & 7);
                const float vv = (c == 0) ? v.x : (c == 1) ? v.y : (c == 2) ? v.z : v.w;
                s_w[k * 128 + 4 * p + qlo] = vv;
            }
        }
        __syncthreads();

        float bq[8];
        #pragma unroll
        for (int c = 0; c < 8; c++) {
            const int qg = qt * 128 + ((c < 4) ? (4 * m + c) : (64 + 4 * m + (c - 4)));
            const int o  = ((qg & 31) << 5) | (qg >> 5);
            bq[c] = __ldg(b2 + o);
        }
        unsigned long long acc[4][4];
        {
            const unsigned long long p0 = pack2(bq[0], bq[1]);
            const unsigned long long p1 = pack2(bq[2], bq[3]);
            const unsigned long long p2 = pack2(bq[4], bq[5]);
            const unsigned long long p3 = pack2(bq[6], bq[7]);
            #pragma unroll
            for (int je = 0; je < 4; je++) {
                acc[je][0] = p0; acc[je][1] = p1; acc[je][2] = p2; acc[je][3] = p3;
            }
        }

        #pragma unroll 8
        for (int k = 0; k < 64; k++) {
            const int s = (k >> 2) & 7;
            const float* wrow = s_w + k * 128;
            const ulonglong2 wA = *(const ulonglong2*)(wrow + 4 * (m ^ s));
            const ulonglong2 wB = *(const ulonglong2*)(wrow + 4 * ((m ^ s) + 16));
            const float* hrow = s_h2 + k * 132 + 2 * ey;
            const ulonglong2 hA = *(const ulonglong2*)(hrow);
            const ulonglong2 hB = *(const ulonglong2*)(hrow + 4);
            acc[0][0] = fma2(wA.x, hA.x, acc[0][0]);
            acc[0][1] = fma2(wA.y, hA.x, acc[0][1]);
            acc[0][2] = fma2(wB.x, hA.x, acc[0][2]);
            acc[0][3] = fma2(wB.y, hA.x, acc[0][3]);
            acc[1][0] = fma2(wA.x, hA.y, acc[1][0]);
            acc[1][1] = fma2(wA.y, hA.y, acc[1][1]);
            acc[1][2] = fma2(wB.x, hA.y, acc[1][2]);
            acc[1][3] = fma2(wB.y, hA.y, acc[1][3]);
            acc[2][0] = fma2(wA.x, hB.x, acc[2][0]);
            acc[2][1] = fma2(wA.y, hB.x, acc[2][1]);
            acc[2][2] = fma2(wB.x, hB.x, acc[2][2]);
            acc[2][3] = fma2(wB.y, hB.x, acc[2][3]);
            acc[3][0] = fma2(wA.x, hB.y, acc[3][0]);
            acc[3][1] = fma2(wA.y, hB.y, acc[3][1]);
            acc[3][2] = fma2(wB.x, hB.y, acc[3][2]);
            acc[3][3] = fma2(wB.y, hB.y, acc[3][3]);
        }

        #pragma unroll
        for (int je = 0; je < 4; je++) {
            float* base = g_A + (e0 + ey + je) * 1024 + qt * 128;
            const float2 a0 = unpack2(acc[je][0]);
            const float2 a1 = unpack2(acc[je][1]);
            const float2 a2 = unpack2(acc[je][2]);
            const float2 a3 = unpack2(acc[je][3]);
            *(float4*)(base + 4 * m) =
                make_float4(fmaxf(a0.x, 0.f), fmaxf(a0.y, 0.f),
                            fmaxf(a1.x, 0.f), fmaxf(a1.y, 0.f));
            *(float4*)(base + 64 + 4 * m) =
                make_float4(fmaxf(a2.x, 0.f), fmaxf(a2.y, 0.f),
                            fmaxf(a3.x, 0.f), fmaxf(a3.y, 0.f));
        }
    }
}

// ============================================================
// Message pass: warp per edge. A read with streaming hint (zero reuse).
// ============================================================
__global__ __launch_bounds__(256) void msg_kernel(const int* __restrict__ edges, int t) {
    const float* __restrict__ xc = (t & 1) ? g_x1 : g_x0;

    const int warp = (blockIdx.x * blockDim.x + threadIdx.x) >> 5;
    const int lane = threadIdx.x & 31;
    if (warp >= N_EDGES) return;

    const int src = __ldg(edges + 2 * warp);
    const int dst = __ldg(edges + 2 * warp + 1);

    const float xv = __ldg(xc + (size_t)src * HDIM + lane);
    const float* Ap = g_A + (size_t)warp * 1024 + lane;

    float acc = 0.f;
    #pragma unroll
    for (int j = 0; j < 32; j++) {
        const float a  = __ldcs(Ap + j * 32);   // streaming: evict-first
        const float xj = __shfl_sync(0xffffffffu, xv, j);
        acc = fmaf(a, xj, acc);
    }

    atomicAdd(g_m + (size_t)src * HDIM + lane, acc);
    if (src != dst) atomicAdd(g_m + (size_t)dst * HDIM + lane, acc);
}

// ============================================================
// GRU cell: 128-thread blocks, thread per node, packed f32x2 math.
// Weights + biases staged in smem; x/m as packed u64 pairs in registers.
// Outputs computed in chunks of 2 (12 independent fma2 chains).
// Also zeroes g_m for the next iteration.
// ============================================================
__global__ __launch_bounds__(128, 4) void gru_kernel(
    const float* __restrict__ W_ih, const float* __restrict__ W_hh,
    const float* __restrict__ b_ih, const float* __restrict__ b_hh,
    float* __restrict__ dout, int t)
{
    __shared__ float s_wih[96 * 64];
    __shared__ float s_whh[96 * 32];
    __shared__ float s_bih[96];
    __shared__ float s_bhh[96];

    const float* __restrict__ xc = (t & 1) ? g_x1 : g_x0;
    float* __restrict__ xo = (t == T_ITERS - 1) ? dout : ((t & 1) ? g_x0 : g_x1);

    for (int idx = threadIdx.x; idx < 96 * 64 / 4; idx += 128)
        ((float4*)s_wih)[idx] = __ldg((const float4*)W_ih + idx);
    for (int idx = threadIdx.x; idx < 96 * 32 / 4; idx += 128)
        ((float4*)s_whh)[idx] = __ldg((const float4*)W_hh + idx);
    if (threadIdx.x < 96) {
        s_bih[threadIdx.x] = __ldg(b_ih + threadIdx.x);
        s_bhh[threadIdx.x] = __ldg(b_hh + threadIdx.x);
    }
    __syncthreads();

    const int n = blockIdx.x * 128 + threadIdx.x;
    const bool valid = (n < N_NODES);
    const int nn_ = valid ? n : (N_NODES - 1);

    // load x, m as packed pairs; zero m for next iteration
    unsigned long long xp[16], mp[16];
    {
        const float4* xq = (const float4*)(xc + (size_t)nn_ * HDIM);
        float4* mq = (float4*)(g_m + (size_t)nn_ * HDIM);
        #pragma unroll
        for (int i = 0; i < 8; i++) {
            float4 v = __ldg(xq + i);
            xp[2*i]   = pack2(v.x, v.y);
            xp[2*i+1] = pack2(v.z, v.w);
            float4 u = mq[i];
            mp[2*i]   = pack2(u.x, u.y);
            mp[2*i+1] = pack2(u.z, u.w);
        }
        if (valid) {
            #pragma unroll
            for (int i = 0; i < 8; i++) mq[i] = make_float4(0.f, 0.f, 0.f, 0.f);
        }
    }

    #pragma unroll 4
    for (int oc = 0; oc < 16; oc++) {
        const int ob = 2 * oc;
        unsigned long long a_ir[2], a_iz[2], a_in[2], a_hr[2], a_hz[2], a_hn[2];
        #pragma unroll
        for (int c = 0; c < 2; c++) {
            a_ir[c] = 0ull; a_iz[c] = 0ull; a_in[c] = 0ull;
            a_hr[c] = 0ull; a_hz[c] = 0ull; a_hn[c] = 0ull;
        }

        #pragma unroll
        for (int c = 0; c < 2; c++) {
            const ulonglong2* wr = (const ulonglong2*)(s_wih + (size_t)(ob + c) * 64);
            const ulonglong2* wz = (const ulonglong2*)(s_wih + (size_t)(32 + ob + c) * 64);
            const ulonglong2* wn = (const ulonglong2*)(s_wih + (size_t)(64 + ob + c) * 64);
            const ulonglong2* vr = (const ulonglong2*)(s_whh + (size_t)(ob + c) * 32);
            const ulonglong2* vz = (const ulonglong2*)(s_whh + (size_t)(32 + ob + c) * 32);
            const ulonglong2* vn = (const ulonglong2*)(s_whh + (size_t)(64 + ob + c) * 32);

            #pragma unroll
            for (int p = 0; p < 8; p++) {
                ulonglong2 w;
                // W_ih x-half
                w = wr[p];
                a_ir[c] = fma2(w.x, xp[2*p], a_ir[c]);
                a_ir[c] = fma2(w.y, xp[2*p+1], a_ir[c]);
                w = wz[p];
                a_iz[c] = fma2(w.x, xp[2*p], a_iz[c]);
                a_iz[c] = fma2(w.y, xp[2*p+1], a_iz[c]);
                w = wn[p];
                a_in[c] = fma2(w.x, xp[2*p], a_in[c]);
                a_in[c] = fma2(w.y, xp[2*p+1], a_in[c]);
                // W_ih m-half
                w = wr[8 + p];
                a_ir[c] = fma2(w.x, mp[2*p], a_ir[c]);
                a_ir[c] = fma2(w.y, mp[2*p+1], a_ir[c]);
                w = wz[8 + p];
                a_iz[c] = fma2(w.x, mp[2*p], a_iz[c]);
                a_iz[c] = fma2(w.y, mp[2*p+1], a_iz[c]);
                w = wn[8 + p];
                a_in[c] = fma2(w.x, mp[2*p], a_in[c]);
                a_in[c] = fma2(w.y, mp[2*p+1], a_in[c]);
                // W_hh (x only)
                w = vr[p];
                a_hr[c] = fma2(w.x, xp[2*p], a_hr[c]);
                a_hr[c] = fma2(w.y, xp[2*p+1], a_hr[c]);
                w = vz[p];
                a_hz[c] = fma2(w.x, xp[2*p], a_hz[c]);
                a_hz[c] = fma2(w.y, xp[2*p+1], a_hz[c]);
                w = vn[p];
                a_hn[c] = fma2(w.x, xp[2*p], a_hn[c]);
                a_hn[c] = fma2(w.y, xp[2*p+1], a_hn[c]);
            }
        }

        const float2 xv = unpack2(xp[oc]);   // x[ob], x[ob+1]
        float outv[2];
        #pragma unroll
        for (int c = 0; c < 2; c++) {
            const float2 fir = unpack2(a_ir[c]);
            const float2 fiz = unpack2(a_iz[c]);
            const float2 fin = unpack2(a_in[c]);
            const float2 fhr = unpack2(a_hr[c]);
            const float2 fhz = unpack2(a_hz[c]);
            const float2 fhn = unpack2(a_hn[c]);
            const float ir = fir.x + fir.y + s_bih[ob + c];
            const float iz = fiz.x + fiz.y + s_bih[32 + ob + c];
            const float in_ = fin.x + fin.y + s_bih[64 + ob + c];
            const float hr = fhr.x + fhr.y + s_bhh[ob + c];
            const float hz = fhz.x + fhz.y + s_bhh[32 + ob + c];
            const float hn = fhn.x + fhn.y + s_bhh[64 + ob + c];
            const float r = sigmoidf_(ir + hr);
            const float z = sigmoidf_(iz + hz);
            const float nn2 = tanhf(in_ + r * hn);
            const float hp = (c == 0) ? xv.x : xv.y;
            outv[c] = (1.f - z) * nn2 + z * hp;
        }
        if (valid) {
            *(float2*)(xo + (size_t)n * HDIM + ob) = make_float2(outv[0], outv[1]);
        }
    }
}

// ============================================================
// launch
// ============================================================
extern "C" void kernel_launch(void* const* d_in, const int* in_sizes, int n_in,
                              void* d_out, int out_size) {
    const float* x     = (const float*)d_in[0];
    const float* ed    = (const float*)d_in[1];
    const int*   edges = (const int*)d_in[2];
    const int wb = n_in - 8;   // weights are the last 8 inputs
    const float* W1   = (const float*)d_in[wb + 0];
    const float* b1   = (const float*)d_in[wb + 1];
    const float* W2   = (const float*)d_in[wb + 2];
    const float* b2   = (const float*)d_in[wb + 3];
    const float* W_ih = (const float*)d_in[wb + 4];
    const float* W_hh = (const float*)d_in[wb + 5];
    const float* b_ih = (const float*)d_in[wb + 6];
    const float* b_hh = (const float*)d_in[wb + 7];
    float* out = (float*)d_out;

    const int n4 = N_NODES * HDIM / 4;
    const int g4 = (n4 + 255) / 256;

    copy_x_kernel<<<g4, 256>>>(x);
    edge_mlp_kernel<<<N_EDGES / 64, 256>>>(ed, W1, b1, W2, b2);

    const int msg_grid = N_EDGES / 8;              // warp per edge, 8 warps/block
    const int gru_grid = (N_NODES + 127) / 128;    // 128-thread blocks

    for (int t = 0; t < T_ITERS; t++) {
        msg_kernel<<<msg_grid, 256>>>(edges, t);
        gru_kernel<<<gru_grid, 128>>>(W_ih, W_hh, b_ih, b_hh, out, t);
    }
}